// round 15
// baseline (speedup 1.0000x reference)
#include <cuda_runtime.h>
#include <cuda_fp16.h>

// GCN 2-layer. Fixed-slab CSR, fp16 gather, TF32 mma.sync GEMM with
// warp-private staging and 32 rows/warp (B-fragment reuse x2).
// conv(x) = dinv[c] * ( sum_{e: col=c} t[row_e] + t[c] ) + b,  t = dinv .* (X@W)

#define NMAX 100000
#define F 64
#define SLAB 64

__device__ __align__(16) float  g_dinv[NMAX];
__device__ __align__(16) __half g_t[NMAX * F];
__device__ __align__(16) float  g_h[NMAX * F];
__device__ int g_fill[NMAX];
__device__ int g_src[NMAX * SLAB];

// ---------------- CSR build ----------------
__global__ void k_zero(int n) {
    int i = blockIdx.x * blockDim.x + threadIdx.x;
    if (i < n) g_fill[i] = 0;
}

__global__ void k_fill(const int* __restrict__ erow, const int* __restrict__ ecol, int E) {
    int e0 = (blockIdx.x * blockDim.x + threadIdx.x) * 4;
    if (e0 + 3 < E) {
        int4 r4 = *reinterpret_cast<const int4*>(erow + e0);
        int4 c4 = *reinterpret_cast<const int4*>(ecol + e0);
        int p0 = atomicAdd(&g_fill[c4.x], 1);
        int p1 = atomicAdd(&g_fill[c4.y], 1);
        int p2 = atomicAdd(&g_fill[c4.z], 1);
        int p3 = atomicAdd(&g_fill[c4.w], 1);
        if (p0 < SLAB) g_src[c4.x * SLAB + p0] = r4.x;
        if (p1 < SLAB) g_src[c4.y * SLAB + p1] = r4.y;
        if (p2 < SLAB) g_src[c4.z * SLAB + p2] = r4.z;
        if (p3 < SLAB) g_src[c4.w * SLAB + p3] = r4.w;
    } else {
        for (int e = e0; e < E; e++) {
            int c = ecol[e];
            int p = atomicAdd(&g_fill[c], 1);
            if (p < SLAB) g_src[c * SLAB + p] = erow[e];
        }
    }
}

__global__ void k_dinv(int n) {
    int i = blockIdx.x * blockDim.x + threadIdx.x;
    if (i < n) {
        int c = g_fill[i];
        g_dinv[i] = rsqrtf((float)(c < SLAB ? c : SLAB) + 1.0f);
    }
}

// ------------- TF32 tensor-core GEMM -------------
__device__ __forceinline__ unsigned cvt_tf32(float f) {
    unsigned u; asm("cvt.rna.tf32.f32 %0, %1;" : "=r"(u) : "f"(f)); return u;
}

#define MMA_TF32(ACC, A, B0, B1)                                            \
    asm volatile(                                                           \
        "mma.sync.aligned.m16n8k8.row.col.f32.tf32.tf32.f32 "               \
        "{%0,%1,%2,%3}, {%4,%5,%6,%7}, {%8,%9}, {%0,%1,%2,%3};"             \
        : "+f"((ACC)[0]), "+f"((ACC)[1]), "+f"((ACC)[2]), "+f"((ACC)[3])    \
        : "r"((A)[0]), "r"((A)[1]), "r"((A)[2]), "r"((A)[3]),               \
          "r"(B0), "r"(B1))

// 256 threads = 8 warps; 32 rows/warp (2 m16 tiles) = 256 rows/block.
// Each Bs fragment LDS.128 feeds 4 MMAs (2 chunks x 2 m-tiles).
template <int K, bool FROM_H>
__global__ void __launch_bounds__(256, 2) k_gemm(const float* __restrict__ Xin,
                                                 const float* __restrict__ W, int n) {
    constexpr int NCH = K / 8;                // k-chunks of 8
    constexpr int NCP = NCH / 2;              // chunk pairs
    constexpr int NH  = K / 64;               // 64-col halves
    extern __shared__ float sm[];
    float* Bs = sm;                           // [j][cp][lane][4]
    float* myX = sm + 8 * NCP * 32 * 4 + (threadIdx.x >> 5) * (32 * 68);

    const int tid  = threadIdx.x;
    const int warp = tid >> 5, lane = tid & 31;
    const int g = lane >> 2, tig = lane & 3;
    const float* X = FROM_H ? g_h : Xin;
    constexpr int KV = K / 4;

    // ---- stage B: coalesced float4 reads of W, scatter-STS into fragments ----
    for (int i4 = tid; i4 < K * 16; i4 += 256) {
        int k = i4 >> 4, colq = i4 & 15;
        float4 w = reinterpret_cast<const float4*>(W)[i4];
        float wv[4] = {w.x, w.y, w.z, w.w};
        int rr = (k >> 2) & 1, c = k >> 3;
        int cp = c >> 1, rbase = 2 * (c & 1) + rr;
#pragma unroll
        for (int e = 0; e < 4; e++) {
            int col = 4 * colq + e;
            Bs[(((col >> 3) * NCP + cp) * 32 + (4 * (col & 7) + (k & 3))) * 4 + rbase] =
                __uint_as_float(cvt_tf32(wv[e]));
        }
    }
    __syncthreads();

    const int rowbase = blockIdx.x * 256 + warp * 32;

    float acc[2][8][4];
#pragma unroll
    for (int mt = 0; mt < 2; mt++)
#pragma unroll
        for (int j = 0; j < 8; j++)
#pragma unroll
            for (int p = 0; p < 4; p++) acc[mt][j][p] = 0.0f;

#pragma unroll
    for (int h = 0; h < NH; h++) {
        __syncwarp();
        // stage this warp's 32 rows x 64 cols: 16x LDG.128, fully coalesced
#pragma unroll
        for (int it = 0; it < 16; it++) {
            int q = it * 32 + lane;
            int r = q >> 4, c4 = q & 15;
            int gr = min(rowbase + r, n - 1);
            float4 v = reinterpret_cast<const float4*>(X)[(size_t)gr * KV + h * 16 + c4];
            v.x = __uint_as_float(cvt_tf32(v.x));
            v.y = __uint_as_float(cvt_tf32(v.y));
            v.z = __uint_as_float(cvt_tf32(v.z));
            v.w = __uint_as_float(cvt_tf32(v.w));
            *reinterpret_cast<float4*>(&myX[r * 68 + 4 * c4]) = v;
        }
        __syncwarp();

#pragma unroll
        for (int cpl = 0; cpl < 4; cpl++) {
            int cp = h * 4 + cpl;
            int lc0 = 16 * cpl, lc1 = lc0 + 8;   // local cols of the two chunks

            unsigned a[2][2][4];   // [mtile][chunk][frag]
#pragma unroll
            for (int mt = 0; mt < 2; mt++) {
                int lr = mt * 16 + g;
                a[mt][0][0] = __float_as_uint(myX[lr * 68 + lc0 + tig]);
                a[mt][0][1] = __float_as_uint(myX[(lr + 8) * 68 + lc0 + tig]);
                a[mt][0][2] = __float_as_uint(myX[lr * 68 + lc0 + tig + 4]);
                a[mt][0][3] = __float_as_uint(myX[(lr + 8) * 68 + lc0 + tig + 4]);
                a[mt][1][0] = __float_as_uint(myX[lr * 68 + lc1 + tig]);
                a[mt][1][1] = __float_as_uint(myX[(lr + 8) * 68 + lc1 + tig]);
                a[mt][1][2] = __float_as_uint(myX[lr * 68 + lc1 + tig + 4]);
                a[mt][1][3] = __float_as_uint(myX[(lr + 8) * 68 + lc1 + tig + 4]);
            }

#pragma unroll
            for (int j = 0; j < 8; j++) {
                float4 bf = *reinterpret_cast<const float4*>(
                    &Bs[((j * NCP + cp) * 32 + lane) * 4]);
                unsigned b0 = __float_as_uint(bf.x), b1 = __float_as_uint(bf.y);
                unsigned b2 = __float_as_uint(bf.z), b3 = __float_as_uint(bf.w);
                MMA_TF32(acc[0][j], a[0][0], b0, b1);
                MMA_TF32(acc[0][j], a[0][1], b2, b3);
                MMA_TF32(acc[1][j], a[1][0], b0, b1);
                MMA_TF32(acc[1][j], a[1][1], b2, b3);
            }
        }
    }

    // ---- epilogue: scale by dinv, fp16, store ----
#pragma unroll
    for (int mt = 0; mt < 2; mt++) {
        const int gr0 = rowbase + mt * 16 + g, gr1 = gr0 + 8;
        if (gr0 < n) {
            float d = g_dinv[gr0];
#pragma unroll
            for (int j = 0; j < 8; j++) {
                __half2 hh = __floats2half2_rn(acc[mt][j][0] * d, acc[mt][j][1] * d);
                *reinterpret_cast<__half2*>(g_t + (size_t)gr0 * F + 8 * j + 2 * tig) = hh;
            }
        }
        if (gr1 < n) {
            float d = g_dinv[gr1];
#pragma unroll
            for (int j = 0; j < 8; j++) {
                __half2 hh = __floats2half2_rn(acc[mt][j][2] * d, acc[mt][j][3] * d);
                *reinterpret_cast<__half2*>(g_t + (size_t)gr1 * F + 8 * j + 2 * tig) = hh;
            }
        }
    }
}

// ------------- aggregate: one warp per node, 8 lanes/edge -------------
template <bool RELU, bool TO_H>
__global__ void k_agg(const float* __restrict__ b, float* __restrict__ out, int n) {
    int node = (blockIdx.x << 3) + (threadIdx.x >> 5);
    if (node >= n) return;
    const int lane = threadIdx.x & 31;
    const int eg = lane >> 3;
    const int fl8 = lane & 7;
    int cnt = g_fill[node];
    cnt = (cnt < SLAB) ? cnt : SLAB;
    const int base = node * SLAB;
    const __half* t = g_t;

    float acc[8] = {0,0,0,0,0,0,0,0};
#pragma unroll 4
    for (int i = eg; i < cnt; i += 4) {
        int r = g_src[base + i];
        uint4 v = *reinterpret_cast<const uint4*>(t + (size_t)r * F + fl8 * 8);
        const __half2* hv = reinterpret_cast<const __half2*>(&v);
#pragma unroll
        for (int j = 0; j < 4; j++) {
            float2 f = __half22float2(hv[j]);
            acc[2 * j]     += f.x;
            acc[2 * j + 1] += f.y;
        }
    }
#pragma unroll
    for (int j = 0; j < 8; j++) {
        acc[j] += __shfl_xor_sync(0xffffffffu, acc[j], 8);
        acc[j] += __shfl_xor_sync(0xffffffffu, acc[j], 16);
    }
    if (eg == 0) {
        uint4 sv = *reinterpret_cast<const uint4*>(t + (size_t)node * F + fl8 * 8);
        const __half2* hv = reinterpret_cast<const __half2*>(&sv);
        float d = rsqrtf((float)cnt + 1.0f);
        float4 b0 = reinterpret_cast<const float4*>(b)[fl8 * 2];
        float4 b1 = reinterpret_cast<const float4*>(b)[fl8 * 2 + 1];
        float o[8];
#pragma unroll
        for (int j = 0; j < 4; j++) {
            float2 f = __half22float2(hv[j]);
            o[2 * j]     = d * (acc[2 * j]     + f.x);
            o[2 * j + 1] = d * (acc[2 * j + 1] + f.y);
        }
        o[0] += b0.x; o[1] += b0.y; o[2] += b0.z; o[3] += b0.w;
        o[4] += b1.x; o[5] += b1.y; o[6] += b1.z; o[7] += b1.w;
        if (RELU) {
#pragma unroll
            for (int j = 0; j < 8; j++) o[j] = fmaxf(o[j], 0.f);
        }
        float* dst = TO_H ? (g_h + (size_t)node * F + fl8 * 8)
                          : (out + (size_t)node * F + fl8 * 8);
        *reinterpret_cast<float4*>(dst)     = make_float4(o[0], o[1], o[2], o[3]);
        *reinterpret_cast<float4*>(dst + 4) = make_float4(o[4], o[5], o[6], o[7]);
    }
}

extern "C" void kernel_launch(void* const* d_in, const int* in_sizes, int n_in,
                              void* d_out, int out_size) {
    const float* x  = (const float*)d_in[0];
    const int*   ei = (const int*)d_in[1];
    const float* W1 = (const float*)d_in[2];
    const float* b1 = (const float*)d_in[3];
    const float* W2 = (const float*)d_in[4];
    const float* b2 = (const float*)d_in[5];
    float* out = (float*)d_out;

    const int E = in_sizes[1] / 2;
    const int N = out_size / F;
    const int* erow = ei;
    const int* ecol = ei + E;

    const int nb = (N + 255) / 256;
    const int fb = (E / 4 + 255) / 256 + 1;
    const int gb = (N + 255) / 256;
    const int ab = (N + 7) / 8;

    // dynamic smem: Bs (8*NCP*32*4 floats) + 8 warp strips (32*68 floats)
    const int smem1 = (8 * 8 * 32 * 4 + 8 * 32 * 68) * 4;   // K=128: ~100 KB
    const int smem2 = (8 * 4 * 32 * 4 + 8 * 32 * 68) * 4;   // K=64:  ~84 KB
    cudaFuncSetAttribute(k_gemm<128, false>,
                         cudaFuncAttributeMaxDynamicSharedMemorySize, smem1);
    cudaFuncSetAttribute(k_gemm<64, true>,
                         cudaFuncAttributeMaxDynamicSharedMemorySize, smem2);

    k_zero<<<nb, 256>>>(N);
    k_fill<<<fb, 256>>>(erow, ecol, E);
    k_dinv<<<nb, 256>>>(N);

    k_gemm<128, false><<<gb, 256, smem1>>>(x, W1, N);
    k_agg<true, true><<<ab, 256>>>(b1, nullptr, N);

    k_gemm<64, true><<<gb, 256, smem2>>>(nullptr, W2, N);
    k_agg<false, false><<<ab, 256>>>(b2, out, N);
}